// round 6
// baseline (speedup 1.0000x reference)
#include <cuda_runtime.h>
#include <cstdint>

#define NV 2048
#define NE 8192
#define D  128

// ---------------- device scratch (static: no runtime allocation) ----------------
__device__ __align__(16) float g_w[NE];                    // 32 KB
__device__ __align__(16) float g_adjA[(size_t)NV * NV];    // 16 MB
__device__ __align__(16) float g_HW[NV * D];               // 1 MB

// ---------------- helpers ----------------
__device__ __forceinline__ uint32_t f2tf32(float x) {
    uint32_t u;
    asm("cvt.rna.tf32.f32 %0, %1;" : "=r"(u) : "f"(x));
    return u;
}

__device__ __forceinline__ void mma_tf32(float* d, const uint32_t* a, const uint32_t* b) {
    asm volatile(
        "mma.sync.aligned.m16n8k8.row.col.f32.tf32.tf32.f32 "
        "{%0,%1,%2,%3}, {%4,%5,%6,%7}, {%8,%9}, {%0,%1,%2,%3};\n"
        : "+f"(d[0]), "+f"(d[1]), "+f"(d[2]), "+f"(d[3])
        : "r"(a[0]), "r"(a[1]), "r"(a[2]), "r"(a[3]), "r"(b[0]), "r"(b[1]));
}

__device__ __forceinline__ void ldsm4(uint32_t* r, uint32_t saddr) {
    asm volatile("ldmatrix.sync.aligned.m8n8.x4.shared.b16 {%0,%1,%2,%3}, [%4];"
                 : "=r"(r[0]), "=r"(r[1]), "=r"(r[2]), "=r"(r[3]) : "r"(saddr));
}

__device__ __forceinline__ void cp_async16(uint32_t saddr, const void* g) {
    asm volatile("cp.async.cg.shared.global [%0], [%1], 16;\n" :: "r"(saddr), "l"(g));
}
__device__ __forceinline__ void cp_commit() { asm volatile("cp.async.commit_group;\n" ::: "memory"); }
__device__ __forceinline__ void cp_wait1()  { asm volatile("cp.async.wait_group 1;\n" ::: "memory"); }

__device__ __forceinline__ uint32_t smem_u32(const void* p) {
    uint32_t a;
    asm("{ .reg .u64 t; cvta.to.shared.u64 t, %1; cvt.u32.u64 %0, t; }" : "=r"(a) : "l"(p));
    return a;
}

// ---------------- kernel 1: w = H_e @ p  (warp per row) ----------------
__global__ void k_w(const float* __restrict__ He, const float* __restrict__ p) {
    int row  = blockIdx.x * 8 + (threadIdx.x >> 5);
    int lane = threadIdx.x & 31;
    const float* r = He + (size_t)row * D;
    float s = 0.f;
#pragma unroll
    for (int j = 0; j < 4; j++) {
        int k = lane + 32 * j;
        s += r[k] * __ldg(p + k);
    }
#pragma unroll
    for (int o = 16; o > 0; o >>= 1) s += __shfl_xor_sync(0xffffffffu, s, o);
    if (lane == 0) g_w[row] = s;
}

// ---------------- kernel 2: HW = H_v @ weight  (8 rows per block) ----------------
__global__ void k_hw(const float* __restrict__ Hv, const float* __restrict__ W) {
    __shared__ float sh[8][D];
    int r0  = blockIdx.x * 8;
    int tid = threadIdx.x;  // 128
#pragma unroll
    for (int r = 0; r < 8; r++) sh[r][tid] = Hv[(size_t)(r0 + r) * D + tid];
    __syncthreads();
    float acc[8] = {};
    for (int k = 0; k < D; k++) {
        float wk = W[k * D + tid];
#pragma unroll
        for (int r = 0; r < 8; r++) acc[r] += sh[r][k] * wk;
    }
#pragma unroll
    for (int r = 0; r < 8; r++) g_HW[(r0 + r) * D + tid] = acc[r];
}

// ---------------- kernel 3: big symmetric GEMM + mask epilogue ----------------
// C = (T*w) @ T^T  (2048x2048, K=8192), upper-tri 128x128 blocks only.
// Raw T loaded for both operands; w-scale + tf32 rounding done in-register.
// 512 threads, 4x4 warp grid, 32x32 warp tiles -> 4 warps/SMSP.
#define BM 128
#define BK 32
#define ASTRIDE (BK + 4)                 // 36 floats; LDSM phases conflict-free
#define TILE_FLOATS (BM * ASTRIDE)       // 4608
#define STAGE_FLOATS (2 * TILE_FLOATS + 48)  // A + B + w(32, padded 48) = 9264
#define NSTAGE 3
#define SMEM_BYTES (NSTAGE * STAGE_FLOATS * 4)  // 111168 B

__global__ void __launch_bounds__(512, 1)
k_gemm1(const float* __restrict__ Tmat, const float* __restrict__ adj_v) {
    // decode upper-triangular block index (16x16 grid of 128-blocks)
    int l = blockIdx.x, bm = 0, rem = 16;
    while (l >= rem) { l -= rem; bm++; rem--; }
    int bn = bm + l;

    extern __shared__ float smem[];
    uint32_t sbase = smem_u32(smem);

    int tid  = threadIdx.x;
    int warp = tid >> 5, lane = tid & 31;
    int wm = warp & 3, wn = warp >> 2;     // 4x4 warp grid: 32 rows x 32 cols each
    int gid = lane >> 2, tig = lane & 3;

    const float* gA = Tmat + (size_t)(bm * BM) * NE;
    const float* gB = Tmat + (size_t)(bn * BM) * NE;

    float acc[2][4][4];
#pragma unroll
    for (int m = 0; m < 2; m++)
#pragma unroll
        for (int n = 0; n < 4; n++)
#pragma unroll
            for (int q = 0; q < 4; q++) acc[m][n][q] = 0.f;

    const int nkt = NE / BK;  // 256

    // stage loader: 1024 16B-chunks per operand over 512 threads (2 each) + w
    auto load_stage = [&](int s, int kt) {
        uint32_t sA = sbase + (uint32_t)(s * STAGE_FLOATS) * 4u;
        uint32_t sB = sA + (uint32_t)TILE_FLOATS * 4u;
#pragma unroll
        for (int i = 0; i < 2; i++) {
            int c = i * 512 + tid;
            int row = c >> 3, c16 = c & 7;
            uint32_t soff = (uint32_t)(row * ASTRIDE + c16 * 4) * 4u;
            cp_async16(sA + soff, gA + (size_t)row * NE + kt * BK + c16 * 4);
            cp_async16(sB + soff, gB + (size_t)row * NE + kt * BK + c16 * 4);
        }
        if (tid < 8)
            cp_async16(sA + (uint32_t)(2 * TILE_FLOATS) * 4u + tid * 16u,
                       g_w + kt * BK + tid * 4);
        cp_commit();
    };

    load_stage(0, 0);
    load_stage(1, 1);

    // LDSM per-lane address offsets (bytes within a stage)
    uint32_t aoff = (uint32_t)((wm * 32 + ((lane >> 3) & 1) * 8 + (lane & 7)) * ASTRIDE
                               + (lane >> 4) * 4) * 4u;
    uint32_t boff = (uint32_t)((wn * 32 + (lane >> 4) * 8 + (lane & 7)) * ASTRIDE
                               + ((lane >> 3) & 1) * 4) * 4u
                  + (uint32_t)TILE_FLOATS * 4u;

    for (int kt = 0; kt < nkt; kt++) {
        cp_wait1();            // stage (kt % NSTAGE) resident
        __syncthreads();
        int s = kt % NSTAGE;
        if (kt + 2 < nkt) load_stage((kt + 2) % NSTAGE, kt + 2);

        uint32_t stb = sbase + (uint32_t)(s * STAGE_FLOATS) * 4u;
        uint32_t aBase = stb + aoff;
        uint32_t bBase = stb + boff;
        uint32_t wAddr = stb + (uint32_t)(2 * TILE_FLOATS) * 4u + (uint32_t)tig * 4u;

        // w values for this k-tile: per lane wv[2*ks] = w[ks*8+tig], wv[2*ks+1] = +4
        float wv[8];
#pragma unroll
        for (int ks = 0; ks < 4; ks++) {
            asm volatile("ld.shared.f32 %0, [%1];" : "=f"(wv[2 * ks])     : "r"(wAddr + ks * 32u));
            asm volatile("ld.shared.f32 %0, [%1];" : "=f"(wv[2 * ks + 1]) : "r"(wAddr + ks * 32u + 16u));
        }

        uint32_t af[2][2][4], bf[2][4][2];

        auto ldfrag = [&](int buf, int ks) {
            uint32_t ka = aBase + (uint32_t)(ks * 32);
            float wlo = wv[2 * ks], whi = wv[2 * ks + 1];
#pragma unroll
            for (int m = 0; m < 2; m++) {
                uint32_t r[4];
                ldsm4(r, ka + (uint32_t)m * (16u * ASTRIDE * 4u));
                af[buf][m][0] = f2tf32(__uint_as_float(r[0]) * wlo);
                af[buf][m][1] = f2tf32(__uint_as_float(r[1]) * wlo);
                af[buf][m][2] = f2tf32(__uint_as_float(r[2]) * whi);
                af[buf][m][3] = f2tf32(__uint_as_float(r[3]) * whi);
            }
            uint32_t kb = bBase + (uint32_t)(ks * 32);
#pragma unroll
            for (int j = 0; j < 2; j++) {
                uint32_t r[4];
                ldsm4(r, kb + (uint32_t)j * (16u * ASTRIDE * 4u));
                bf[buf][2 * j][0]     = f2tf32(__uint_as_float(r[0]));
                bf[buf][2 * j][1]     = f2tf32(__uint_as_float(r[1]));
                bf[buf][2 * j + 1][0] = f2tf32(__uint_as_float(r[2]));
                bf[buf][2 * j + 1][1] = f2tf32(__uint_as_float(r[3]));
            }
        };

        ldfrag(0, 0);
#pragma unroll
        for (int ks = 0; ks < 4; ks++) {
            if (ks < 3) ldfrag((ks + 1) & 1, ks + 1);
            int b = ks & 1;
#pragma unroll
            for (int m = 0; m < 2; m++)
#pragma unroll
                for (int n = 0; n < 4; n++) mma_tf32(acc[m][n], af[b][m], bf[b][n]);
        }
    }

    // epilogue: mask + adj_v multiply; mirror into (bn,bm) block when off-diagonal
    bool offdiag = (bm != bn);
#pragma unroll
    for (int m = 0; m < 2; m++) {
        int i0 = bm * BM + wm * 32 + m * 16 + gid;
#pragma unroll
        for (int n = 0; n < 4; n++) {
            int j0 = bn * BM + wn * 32 + n * 8 + 2 * tig;
#pragma unroll
            for (int q = 0; q < 4; q++) {
                int i = i0 + (q >> 1) * 8;
                int j = j0 + (q & 1);
                float v = acc[m][n][q];
                float m1 = (i == j) ? 1.0f : v;
                g_adjA[(size_t)i * NV + j] = m1 * adj_v[(size_t)i * NV + j];
                if (offdiag)  // i != j guaranteed
                    g_adjA[(size_t)j * NV + i] = v * adj_v[(size_t)j * NV + i];
            }
        }
    }
}

// ---------------- kernel 4: ret = adjA @ HW + bias (fp32 SIMT) ----------------
__global__ void __launch_bounds__(256)
k_gemm2(const float* __restrict__ bias, float* __restrict__ out) {
    __shared__ float sa[16][33];
    int tid  = threadIdx.x;       // 256
    int col  = tid & 127;
    int half = tid >> 7;
    int r0   = blockIdx.x * 16;
    float acc[8] = {};
    for (int kt = 0; kt < NV / 32; kt++) {
        __syncthreads();
#pragma unroll
        for (int i = 0; i < 2; i++) {
            int c = i * 256 + tid;
            int r = c >> 5, k = c & 31;
            sa[r][k] = g_adjA[(size_t)(r0 + r) * NV + kt * 32 + k];
        }
        __syncthreads();
#pragma unroll 8
        for (int k = 0; k < 32; k++) {
            float hw = g_HW[(kt * 32 + k) * D + col];
#pragma unroll
            for (int r = 0; r < 8; r++) acc[r] += sa[half * 8 + r][k] * hw;
        }
    }
    float b = bias[col];
#pragma unroll
    for (int r = 0; r < 8; r++)
        out[(size_t)(r0 + half * 8 + r) * D + col] = acc[r] + b;
}

// ---------------- launch ----------------
extern "C" void kernel_launch(void* const* d_in, const int* in_sizes, int n_in,
                              void* d_out, int out_size) {
    const float* H_v   = (const float*)d_in[0];
    const float* H_e   = (const float*)d_in[1];
    // d_in[2] = adj_e : UNUSED by the reference graph (node_layer branch)
    const float* adj_v = (const float*)d_in[3];
    const float* T     = (const float*)d_in[4];
    const float* W     = (const float*)d_in[5];
    const float* p     = (const float*)d_in[6];
    const float* bias  = (const float*)d_in[7];
    float* out = (float*)d_out;

    k_w<<<NE / 8, 256>>>(H_e, p);
    k_hw<<<NV / 8, 128>>>(H_v, W);

    cudaFuncSetAttribute(k_gemm1, cudaFuncAttributeMaxDynamicSharedMemorySize, SMEM_BYTES);
    k_gemm1<<<136, 512, SMEM_BYTES>>>(T, adj_v);

    k_gemm2<<<NV / 16, 256>>>(bias, out);

    // second output: H_e passthrough, concatenated after ret
    if (out_size >= NV * D + NE * D) {
        cudaMemcpyAsync(out + NV * D, H_e, (size_t)NE * D * sizeof(float),
                        cudaMemcpyDeviceToDevice, 0);
    }
}

// round 7
// speedup vs baseline: 1.6977x; 1.6977x over previous
#include <cuda_runtime.h>
#include <cstdint>

#define NV 2048
#define NE 8192
#define D  128

// ---------------- device scratch (static: no runtime allocation) ----------------
__device__ __align__(16) float g_w[NE];                    // 32 KB
__device__ __align__(16) float g_Tw[(size_t)NV * NE];      // 64 MB  tf32(T*w)
__device__ __align__(16) float g_Ttf[(size_t)NV * NE];     // 64 MB  tf32(T)
__device__ __align__(16) float g_adjA[(size_t)NV * NV];    // 16 MB
__device__ __align__(16) float g_HW[NV * D];               // 1 MB

// ---------------- helpers ----------------
__device__ __forceinline__ uint32_t f2tf32(float x) {
    uint32_t u;
    asm("cvt.rna.tf32.f32 %0, %1;" : "=r"(u) : "f"(x));
    return u;
}

__device__ __forceinline__ void mma_tf32(float* d, const uint32_t* a, const uint32_t* b) {
    asm volatile(
        "mma.sync.aligned.m16n8k8.row.col.f32.tf32.tf32.f32 "
        "{%0,%1,%2,%3}, {%4,%5,%6,%7}, {%8,%9}, {%0,%1,%2,%3};\n"
        : "+f"(d[0]), "+f"(d[1]), "+f"(d[2]), "+f"(d[3])
        : "r"(a[0]), "r"(a[1]), "r"(a[2]), "r"(a[3]), "r"(b[0]), "r"(b[1]));
}

__device__ __forceinline__ void ldsm4(uint32_t* r, uint32_t saddr) {
    asm volatile("ldmatrix.sync.aligned.m8n8.x4.shared.b16 {%0,%1,%2,%3}, [%4];"
                 : "=r"(r[0]), "=r"(r[1]), "=r"(r[2]), "=r"(r[3]) : "r"(saddr));
}

__device__ __forceinline__ void cp_async16(uint32_t saddr, const void* g) {
    asm volatile("cp.async.cg.shared.global [%0], [%1], 16;\n" :: "r"(saddr), "l"(g));
}
__device__ __forceinline__ void cp_commit() { asm volatile("cp.async.commit_group;\n" ::: "memory"); }
__device__ __forceinline__ void cp_wait1()  { asm volatile("cp.async.wait_group 1;\n" ::: "memory"); }

__device__ __forceinline__ uint32_t smem_u32(const void* p) {
    uint32_t a;
    asm("{ .reg .u64 t; cvta.to.shared.u64 t, %1; cvt.u32.u64 %0, t; }" : "=r"(a) : "l"(p));
    return a;
}

// ---------------- kernel 1: w = H_e @ p  (warp per row) ----------------
__global__ void k_w(const float* __restrict__ He, const float* __restrict__ p) {
    int row  = blockIdx.x * 8 + (threadIdx.x >> 5);
    int lane = threadIdx.x & 31;
    const float* r = He + (size_t)row * D;
    float s = 0.f;
#pragma unroll
    for (int j = 0; j < 4; j++) {
        int k = lane + 32 * j;
        s += r[k] * __ldg(p + k);
    }
#pragma unroll
    for (int o = 16; o > 0; o >>= 1) s += __shfl_xor_sync(0xffffffffu, s, o);
    if (lane == 0) g_w[row] = s;
}

// ---------------- kernel 2: Tw = tf32(T*w), Ttf = tf32(T)  (one read of T) ----------------
__global__ void __launch_bounds__(256)
k_prep(const float* __restrict__ T) {
    const size_t stride = (size_t)gridDim.x * blockDim.x;   // 524288
    size_t c = (size_t)blockIdx.x * blockDim.x + threadIdx.x;
#pragma unroll
    for (int it = 0; it < 8; it++, c += stride) {
        size_t e  = c * 4;
        int col = (int)(e & (size_t)(NE - 1));
        float4 t = *reinterpret_cast<const float4*>(T + e);
        float4 w = *reinterpret_cast<const float4*>(g_w + col);
        float4 o, r;
        o.x = __uint_as_float(f2tf32(t.x * w.x));
        o.y = __uint_as_float(f2tf32(t.y * w.y));
        o.z = __uint_as_float(f2tf32(t.z * w.z));
        o.w = __uint_as_float(f2tf32(t.w * w.w));
        r.x = __uint_as_float(f2tf32(t.x));
        r.y = __uint_as_float(f2tf32(t.y));
        r.z = __uint_as_float(f2tf32(t.z));
        r.w = __uint_as_float(f2tf32(t.w));
        *reinterpret_cast<float4*>(g_Tw + e)  = o;
        *reinterpret_cast<float4*>(g_Ttf + e) = r;
    }
}

// ---------------- kernel 3: HW = H_v @ weight  (8 rows per block) ----------------
__global__ void k_hw(const float* __restrict__ Hv, const float* __restrict__ W) {
    __shared__ float sh[8][D];
    int r0  = blockIdx.x * 8;
    int tid = threadIdx.x;  // 128
#pragma unroll
    for (int r = 0; r < 8; r++) sh[r][tid] = Hv[(size_t)(r0 + r) * D + tid];
    __syncthreads();
    float acc[8] = {};
    for (int k = 0; k < D; k++) {
        float wk = W[k * D + tid];
#pragma unroll
        for (int r = 0; r < 8; r++) acc[r] += sh[r][k] * wk;
    }
#pragma unroll
    for (int r = 0; r < 8; r++) g_HW[(r0 + r) * D + tid] = acc[r];
}

// ---------------- kernel 4: big symmetric GEMM + mask epilogue (R4 proven) ----------------
// C = Tw @ Ttf^T  (2048x2048, K=8192), only upper-tri 128x128 blocks computed.
#define BM 128
#define BK 32
#define ASTRIDE (BK + 4)                 // 36 floats; LDSM phases conflict-free
#define STAGE_FLOATS (2 * BM * ASTRIDE)  // A + B tile per stage = 9216 floats
#define NSTAGE 3
#define SMEM_BYTES (NSTAGE * STAGE_FLOATS * 4)  // 110592 B

__global__ void __launch_bounds__(256, 1)
k_gemm1(const float* __restrict__ adj_v) {
    // decode upper-triangular block index (16x16 grid of 128-blocks)
    int l = blockIdx.x, bm = 0, rem = 16;
    while (l >= rem) { l -= rem; bm++; rem--; }
    int bn = bm + l;

    extern __shared__ float smem[];
    uint32_t sbase = smem_u32(smem);

    int tid  = threadIdx.x;
    int warp = tid >> 5, lane = tid & 31;
    int wm = warp & 3, wn = warp >> 2;     // 4x2 warp grid: warp = 32 rows x 64 cols
    int gid = lane >> 2, tig = lane & 3;

    const float* gA = g_Tw  + (size_t)(bm * BM) * NE;
    const float* gB = g_Ttf + (size_t)(bn * BM) * NE;

    float acc[2][8][4];
#pragma unroll
    for (int m = 0; m < 2; m++)
#pragma unroll
        for (int n = 0; n < 8; n++)
#pragma unroll
            for (int q = 0; q < 4; q++) acc[m][n][q] = 0.f;

    const int nkt = NE / BK;  // 256

    auto load_stage = [&](int s, int kt) {
        uint32_t sA = sbase + (uint32_t)(s * STAGE_FLOATS) * 4u;
        uint32_t sB = sA + (uint32_t)(BM * ASTRIDE) * 4u;
#pragma unroll
        for (int i = 0; i < 4; i++) {
            int c = i * 256 + tid;
            int row = c >> 3, c16 = c & 7;
            uint32_t soff = (uint32_t)(row * ASTRIDE + c16 * 4) * 4u;
            cp_async16(sA + soff, gA + (size_t)row * NE + kt * BK + c16 * 4);
            cp_async16(sB + soff, gB + (size_t)row * NE + kt * BK + c16 * 4);
        }
        cp_commit();
    };

    load_stage(0, 0);
    load_stage(1, 1);

    uint32_t aoff = (uint32_t)((wm * 32 + ((lane >> 3) & 1) * 8 + (lane & 7)) * ASTRIDE
                               + (lane >> 4) * 4) * 4u;
    uint32_t boff = (uint32_t)((wn * 64 + (lane >> 4) * 8 + (lane & 7)) * ASTRIDE
                               + ((lane >> 3) & 1) * 4) * 4u
                  + (uint32_t)(BM * ASTRIDE) * 4u;

    for (int kt = 0; kt < nkt; kt++) {
        cp_wait1();
        __syncthreads();
        int s = kt % NSTAGE;
        if (kt + 2 < nkt) load_stage((kt + 2) % NSTAGE, kt + 2);

        uint32_t stb = sbase + (uint32_t)(s * STAGE_FLOATS) * 4u;
        uint32_t aBase = stb + aoff;
        uint32_t bBase = stb + boff;

        uint32_t af[2][2][4], bf[2][8][2];

        auto ldfrag = [&](int buf, int ks) {
            uint32_t ka = aBase + (uint32_t)(ks * 32);
            ldsm4(af[buf][0], ka);
            ldsm4(af[buf][1], ka + 16u * ASTRIDE * 4u);
            uint32_t kb = bBase + (uint32_t)(ks * 32);
#pragma unroll
            for (int j = 0; j < 4; j++) {
                uint32_t r[4];
                ldsm4(r, kb + (uint32_t)j * (16u * ASTRIDE * 4u));
                bf[buf][2 * j][0]     = r[0];
                bf[buf][2 * j][1]     = r[1];
                bf[buf][2 * j + 1][0] = r[2];
                bf[buf][2 * j + 1][1] = r[3];
            }
        };

        ldfrag(0, 0);
#pragma unroll
        for (int ks = 0; ks < 4; ks++) {
            if (ks < 3) ldfrag((ks + 1) & 1, ks + 1);
            int b = ks & 1;
#pragma unroll
            for (int m = 0; m < 2; m++)
#pragma unroll
                for (int n = 0; n < 8; n++) mma_tf32(acc[m][n], af[b][m], bf[b][n]);
        }
    }

    bool offdiag = (bm != bn);
#pragma unroll
    for (int m = 0; m < 2; m++) {
        int i0 = bm * BM + wm * 32 + m * 16 + gid;
#pragma unroll
        for (int n = 0; n < 8; n++) {
            int j0 = bn * BM + wn * 64 + n * 8 + 2 * tig;
#pragma unroll
            for (int q = 0; q < 4; q++) {
                int i = i0 + (q >> 1) * 8;
                int j = j0 + (q & 1);
                float v = acc[m][n][q];
                float m1 = (i == j) ? 1.0f : v;
                g_adjA[(size_t)i * NV + j] = m1 * adj_v[(size_t)i * NV + j];
                if (offdiag)
                    g_adjA[(size_t)j * NV + i] = v * adj_v[(size_t)j * NV + i];
            }
        }
    }
}

// ---------------- kernel 5: ret = adjA @ HW + bias (pipelined fp32 SIMT) ----------------
// 128 CTAs x 256 thr; tile 16 rows x 128 cols; K=2048, BK2=32, 3-stage cp.async.
#define BK2 32
#define H_FLOATS (BK2 * D)           // 4096 floats (HW tile)
#define A_STRIDE 36                  // adjA tile row stride (16B aligned, conflict-free)
#define A_FLOATS (16 * A_STRIDE)     // 576 floats
#define STG2_FLOATS (H_FLOATS + A_FLOATS)   // 4672
#define NSTG2 3
#define SMEM2_BYTES (NSTG2 * STG2_FLOATS * 4)  // 56064 B

__global__ void __launch_bounds__(256, 1)
k_gemm2(const float* __restrict__ bias, float* __restrict__ out) {
    extern __shared__ float sm2[];
    uint32_t sb = smem_u32(sm2);

    int tid  = threadIdx.x;
    int warp = tid >> 5, lane = tid & 31;
    int colb = (warp & 3) * 32 + (lane & 7) * 4;   // this thread's 4 output cols
    int rowb = (warp >> 2) * 8 + (lane >> 3) * 2;  // this thread's 2 output rows
    int r0   = blockIdx.x * 16;

    const int nkt = NV / BK2;  // 64

    auto load_stage = [&](int s, int kt) {
        uint32_t base = sb + (uint32_t)(s * STG2_FLOATS) * 4u;
        // HW tile: 32 rows x 128 floats = 1024 16B-chunks over 256 threads
#pragma unroll
        for (int i = 0; i < 4; i++) {
            int c = i * 256 + tid;
            int row = c >> 5, cic = c & 31;
            cp_async16(base + (uint32_t)(row * D + cic * 4) * 4u,
                       g_HW + (size_t)(kt * BK2 + row) * D + cic * 4);
        }
        // adjA tile: 16 rows x 32 floats = 128 chunks
        if (tid < 128) {
            int row = tid >> 3, cic = tid & 7;
            cp_async16(base + (uint32_t)(H_FLOATS + row * A_STRIDE + cic * 4) * 4u,
                       g_adjA + (size_t)(r0 + row) * NV + kt * BK2 + cic * 4);
        }
        cp_commit();
    };

    load_stage(0, 0);
    load_stage(1, 1);

    float4 acc0 = {0.f, 0.f, 0.f, 0.f};
    float4 acc1 = {0.f, 0.f, 0.f, 0.f};

    for (int kt = 0; kt < nkt; kt++) {
        cp_wait1();
        __syncthreads();
        int s = kt % NSTG2;
        if (kt + 2 < nkt) load_stage((kt + 2) % NSTG2, kt + 2);

        const float* sH = sm2 + s * STG2_FLOATS;
        const float* sA = sH + H_FLOATS;
        const float* a0p = sA + rowb * A_STRIDE;
        const float* a1p = a0p + A_STRIDE;

#pragma unroll
        for (int k4 = 0; k4 < BK2 / 4; k4++) {
            float4 a0 = *reinterpret_cast<const float4*>(a0p + k4 * 4);
            float4 a1 = *reinterpret_cast<const float4*>(a1p + k4 * 4);
#pragma unroll
            for (int kk = 0; kk < 4; kk++) {
                float4 h = *reinterpret_cast<const float4*>(sH + (k4 * 4 + kk) * D + colb);
                float av0 = (kk == 0) ? a0.x : (kk == 1) ? a0.y : (kk == 2) ? a0.z : a0.w;
                float av1 = (kk == 0) ? a1.x : (kk == 1) ? a1.y : (kk == 2) ? a1.z : a1.w;
                acc0.x += av0 * h.x; acc0.y += av0 * h.y;
                acc0.z += av0 * h.z; acc0.w += av0 * h.w;
                acc1.x += av1 * h.x; acc1.y += av1 * h.y;
                acc1.z += av1 * h.z; acc1.w += av1 * h.w;
            }
        }
    }

    float4 b = *reinterpret_cast<const float4*>(bias + colb);
    acc0.x += b.x; acc0.y += b.y; acc0.z += b.z; acc0.w += b.w;
    acc1.x += b.x; acc1.y += b.y; acc1.z += b.z; acc1.w += b.w;
    *reinterpret_cast<float4*>(out + (size_t)(r0 + rowb) * D + colb)     = acc0;
    *reinterpret_cast<float4*>(out + (size_t)(r0 + rowb + 1) * D + colb) = acc1;
}

// ---------------- launch ----------------
extern "C" void kernel_launch(void* const* d_in, const int* in_sizes, int n_in,
                              void* d_out, int out_size) {
    const float* H_v   = (const float*)d_in[0];
    const float* H_e   = (const float*)d_in[1];
    // d_in[2] = adj_e : UNUSED by the reference graph (node_layer branch)
    const float* adj_v = (const float*)d_in[3];
    const float* T     = (const float*)d_in[4];
    const float* W     = (const float*)d_in[5];
    const float* p     = (const float*)d_in[6];
    const float* bias  = (const float*)d_in[7];
    float* out = (float*)d_out;

    k_w<<<NE / 8, 256>>>(H_e, p);
    k_prep<<<2048, 256>>>(T);
    k_hw<<<NV / 8, 128>>>(H_v, W);

    cudaFuncSetAttribute(k_gemm1, cudaFuncAttributeMaxDynamicSharedMemorySize, SMEM_BYTES);
    k_gemm1<<<136, 256, SMEM_BYTES>>>(adj_v);

    cudaFuncSetAttribute(k_gemm2, cudaFuncAttributeMaxDynamicSharedMemorySize, SMEM2_BYTES);
    k_gemm2<<<NV / 16, 256, SMEM2_BYTES>>>(bias, out);

    // second output: H_e passthrough, concatenated after ret
    if (out_size >= NV * D + NE * D) {
        cudaMemcpyAsync(out + NV * D, H_e, (size_t)NE * D * sizeof(float),
                        cudaMemcpyDeviceToDevice, 0);
    }
}

// round 8
// speedup vs baseline: 1.7562x; 1.0344x over previous
#include <cuda_runtime.h>
#include <cstdint>

#define NV 2048
#define NE 8192
#define D  128

// ---------------- device scratch (static: no runtime allocation) ----------------
__device__ __align__(16) float g_w[NE];                    // 32 KB
__device__ __align__(16) float g_Tw[(size_t)NV * NE];      // 64 MB  tf32(T*w)
__device__ __align__(16) float g_Ttf[(size_t)NV * NE];     // 64 MB  tf32(T)
__device__ __align__(16) float g_adjA[(size_t)NV * NV];    // 16 MB
__device__ __align__(16) float g_HW[NV * D];               // 1 MB

// ---------------- helpers ----------------
__device__ __forceinline__ uint32_t f2tf32(float x) {
    uint32_t u;
    asm("cvt.rna.tf32.f32 %0, %1;" : "=r"(u) : "f"(x));
    return u;
}

__device__ __forceinline__ void mma_tf32(float* d, const uint32_t* a, const uint32_t* b) {
    asm volatile(
        "mma.sync.aligned.m16n8k8.row.col.f32.tf32.tf32.f32 "
        "{%0,%1,%2,%3}, {%4,%5,%6,%7}, {%8,%9}, {%0,%1,%2,%3};\n"
        : "+f"(d[0]), "+f"(d[1]), "+f"(d[2]), "+f"(d[3])
        : "r"(a[0]), "r"(a[1]), "r"(a[2]), "r"(a[3]), "r"(b[0]), "r"(b[1]));
}

__device__ __forceinline__ void ldsm4(uint32_t* r, uint32_t saddr) {
    asm volatile("ldmatrix.sync.aligned.m8n8.x4.shared.b16 {%0,%1,%2,%3}, [%4];"
                 : "=r"(r[0]), "=r"(r[1]), "=r"(r[2]), "=r"(r[3]) : "r"(saddr));
}

__device__ __forceinline__ void cp_async16(uint32_t saddr, const void* g) {
    asm volatile("cp.async.cg.shared.global [%0], [%1], 16;\n" :: "r"(saddr), "l"(g));
}
__device__ __forceinline__ void cp_commit() { asm volatile("cp.async.commit_group;\n" ::: "memory"); }
__device__ __forceinline__ void cp_wait1()  { asm volatile("cp.async.wait_group 1;\n" ::: "memory"); }
__device__ __forceinline__ void cp_wait0()  { asm volatile("cp.async.wait_group 0;\n" ::: "memory"); }

__device__ __forceinline__ uint32_t smem_u32(const void* p) {
    uint32_t a;
    asm("{ .reg .u64 t; cvta.to.shared.u64 t, %1; cvt.u32.u64 %0, t; }" : "=r"(a) : "l"(p));
    return a;
}

// ---------------- kernel 1: w = H_e @ p  (warp per row) ----------------
__global__ void k_w(const float* __restrict__ He, const float* __restrict__ p) {
    int row  = blockIdx.x * 8 + (threadIdx.x >> 5);
    int lane = threadIdx.x & 31;
    const float* r = He + (size_t)row * D;
    float s = 0.f;
#pragma unroll
    for (int j = 0; j < 4; j++) {
        int k = lane + 32 * j;
        s += r[k] * __ldg(p + k);
    }
#pragma unroll
    for (int o = 16; o > 0; o >>= 1) s += __shfl_xor_sync(0xffffffffu, s, o);
    if (lane == 0) g_w[row] = s;
}

// ---------------- kernel 2: Tw = tf32(T*w), Ttf = tf32(T)  (one read of T) ----------------
__global__ void __launch_bounds__(256)
k_prep(const float* __restrict__ T) {
    const size_t stride = (size_t)gridDim.x * blockDim.x;   // 524288
    size_t c = (size_t)blockIdx.x * blockDim.x + threadIdx.x;
#pragma unroll
    for (int it = 0; it < 8; it++, c += stride) {
        size_t e  = c * 4;
        int col = (int)(e & (size_t)(NE - 1));
        float4 t = *reinterpret_cast<const float4*>(T + e);
        float4 w = *reinterpret_cast<const float4*>(g_w + col);
        float4 o, r;
        o.x = __uint_as_float(f2tf32(t.x * w.x));
        o.y = __uint_as_float(f2tf32(t.y * w.y));
        o.z = __uint_as_float(f2tf32(t.z * w.z));
        o.w = __uint_as_float(f2tf32(t.w * w.w));
        r.x = __uint_as_float(f2tf32(t.x));
        r.y = __uint_as_float(f2tf32(t.y));
        r.z = __uint_as_float(f2tf32(t.z));
        r.w = __uint_as_float(f2tf32(t.w));
        *reinterpret_cast<float4*>(g_Tw + e)  = o;
        *reinterpret_cast<float4*>(g_Ttf + e) = r;
    }
}

// ---------------- kernel 3: HW = H_v @ weight  (8 rows per block) ----------------
__global__ void k_hw(const float* __restrict__ Hv, const float* __restrict__ W) {
    __shared__ float sh[8][D];
    int r0  = blockIdx.x * 8;
    int tid = threadIdx.x;  // 128
#pragma unroll
    for (int r = 0; r < 8; r++) sh[r][tid] = Hv[(size_t)(r0 + r) * D + tid];
    __syncthreads();
    float acc[8] = {};
    for (int k = 0; k < D; k++) {
        float wk = W[k * D + tid];
#pragma unroll
        for (int r = 0; r < 8; r++) acc[r] += sh[r][k] * wk;
    }
#pragma unroll
    for (int r = 0; r < 8; r++) g_HW[(r0 + r) * D + tid] = acc[r];
}

// ---------------- kernel 4: big symmetric GEMM, 512 thr, warp-level K-split ----------------
// C = Tw @ Ttf^T  (2048x2048, K=8192), upper-tri 128x128 blocks only.
// 16 warps = 2 teams x (4x2 grid of 32x64 warp tiles). Team t computes
// k in [16t, 16t+16) of each BK=32 tile; partials combined through smem.
#define BM 128
#define BK 32
#define ASTRIDE (BK + 4)                 // 36 floats; LDSM phases conflict-free
#define STAGE_FLOATS (2 * BM * ASTRIDE)  // A + B tile per stage = 9216 floats
#define NSTAGE 3
#define SMEM_BYTES (NSTAGE * STAGE_FLOATS * 4)  // 110592 B
#define CSTRIDE 132                      // epilogue reduce buffer row stride

__global__ void __launch_bounds__(512, 1)
k_gemm1(const float* __restrict__ adj_v) {
    // decode upper-triangular block index (16x16 grid of 128-blocks)
    int l = blockIdx.x, bm = 0, rem = 16;
    while (l >= rem) { l -= rem; bm++; rem--; }
    int bn = bm + l;

    extern __shared__ float smem[];
    uint32_t sbase = smem_u32(smem);

    int tid  = threadIdx.x;
    int warp = tid >> 5, lane = tid & 31;
    int team = warp >> 3;                  // 0 or 1: K-half
    int w8   = warp & 7;
    int wm = w8 & 3, wn = w8 >> 2;         // 4x2 grid: warp = 32 rows x 64 cols
    int gid = lane >> 2, tig = lane & 3;

    const float* gA = g_Tw  + (size_t)(bm * BM) * NE;
    const float* gB = g_Ttf + (size_t)(bn * BM) * NE;

    float acc[2][8][4];
#pragma unroll
    for (int m = 0; m < 2; m++)
#pragma unroll
        for (int n = 0; n < 8; n++)
#pragma unroll
            for (int q = 0; q < 4; q++) acc[m][n][q] = 0.f;

    const int nkt = NE / BK;  // 256

    // stage loader: 1024 16B-chunks per operand over 512 threads (2 each)
    auto load_stage = [&](int s, int kt) {
        uint32_t sA = sbase + (uint32_t)(s * STAGE_FLOATS) * 4u;
        uint32_t sB = sA + (uint32_t)(BM * ASTRIDE) * 4u;
#pragma unroll
        for (int i = 0; i < 2; i++) {
            int c = i * 512 + tid;
            int row = c >> 3, c16 = c & 7;
            uint32_t soff = (uint32_t)(row * ASTRIDE + c16 * 4) * 4u;
            cp_async16(sA + soff, gA + (size_t)row * NE + kt * BK + c16 * 4);
            cp_async16(sB + soff, gB + (size_t)row * NE + kt * BK + c16 * 4);
        }
        cp_commit();
    };

    load_stage(0, 0);
    load_stage(1, 1);

    // LDSM per-lane address offsets (bytes within a stage); ks adds 32B each
    uint32_t aoff = (uint32_t)((wm * 32 + ((lane >> 3) & 1) * 8 + (lane & 7)) * ASTRIDE
                               + (lane >> 4) * 4) * 4u;
    uint32_t boff = (uint32_t)((wn * 64 + (lane >> 4) * 8 + (lane & 7)) * ASTRIDE
                               + ((lane >> 3) & 1) * 4) * 4u
                  + (uint32_t)(BM * ASTRIDE) * 4u;
    int ks0 = team * 2;   // this team's two k-substeps per tile

    for (int kt = 0; kt < nkt; kt++) {
        if (kt + 1 < nkt) cp_wait1(); else cp_wait0();
        __syncthreads();
        int s = kt % NSTAGE;
        if (kt + 2 < nkt) load_stage((kt + 2) % NSTAGE, kt + 2);

        uint32_t stb = sbase + (uint32_t)(s * STAGE_FLOATS) * 4u;
        uint32_t aBase = stb + aoff;
        uint32_t bBase = stb + boff;

#pragma unroll
        for (int sk = 0; sk < 2; sk++) {
            int ks = ks0 + sk;
            uint32_t af[2][4], bf[8][2];
            uint32_t ka = aBase + (uint32_t)(ks * 32);
            ldsm4(af[0], ka);
            ldsm4(af[1], ka + 16u * ASTRIDE * 4u);
            uint32_t kb = bBase + (uint32_t)(ks * 32);
#pragma unroll
            for (int j = 0; j < 4; j++) {
                uint32_t r[4];
                ldsm4(r, kb + (uint32_t)j * (16u * ASTRIDE * 4u));
                bf[2 * j][0]     = r[0];
                bf[2 * j][1]     = r[1];
                bf[2 * j + 1][0] = r[2];
                bf[2 * j + 1][1] = r[3];
            }
#pragma unroll
            for (int m = 0; m < 2; m++)
#pragma unroll
                for (int n = 0; n < 8; n++) mma_tf32(acc[m][n], af[m], bf[n]);
        }
    }

    // ---- combine team partials through smem, then masked epilogue ----
    __syncthreads();
    if (team == 1) {
#pragma unroll
        for (int m = 0; m < 2; m++) {
            int il = wm * 32 + m * 16 + gid;
#pragma unroll
            for (int n = 0; n < 8; n++) {
                int jl = wn * 64 + n * 8 + 2 * tig;
#pragma unroll
                for (int q = 0; q < 4; q++)
                    smem[(il + (q >> 1) * 8) * CSTRIDE + jl + (q & 1)] = acc[m][n][q];
            }
        }
    }
    __syncthreads();

    if (team == 0) {
        bool offdiag = (bm != bn);
#pragma unroll
        for (int m = 0; m < 2; m++) {
            int il0 = wm * 32 + m * 16 + gid;
#pragma unroll
            for (int n = 0; n < 8; n++) {
                int jl0 = wn * 64 + n * 8 + 2 * tig;
#pragma unroll
                for (int q = 0; q < 4; q++) {
                    int il = il0 + (q >> 1) * 8;
                    int jl = jl0 + (q & 1);
                    int i = bm * BM + il;
                    int j = bn * BM + jl;
                    float v = acc[m][n][q] + smem[il * CSTRIDE + jl];
                    float m1 = (i == j) ? 1.0f : v;
                    g_adjA[(size_t)i * NV + j] = m1 * adj_v[(size_t)i * NV + j];
                    if (offdiag)  // i != j guaranteed
                        g_adjA[(size_t)j * NV + i] = v * adj_v[(size_t)j * NV + i];
                }
            }
        }
    }
}

// ---------------- kernel 5: ret = adjA @ HW + bias (pipelined fp32 SIMT) ----------------
#define BK2 32
#define H_FLOATS (BK2 * D)           // 4096 floats (HW tile)
#define A_STRIDE 36
#define A_FLOATS (16 * A_STRIDE)     // 576 floats
#define STG2_FLOATS (H_FLOATS + A_FLOATS)   // 4672
#define NSTG2 3
#define SMEM2_BYTES (NSTG2 * STG2_FLOATS * 4)  // 56064 B

__global__ void __launch_bounds__(256, 1)
k_gemm2(const float* __restrict__ bias, float* __restrict__ out) {
    extern __shared__ float sm2[];
    uint32_t sb = smem_u32(sm2);

    int tid  = threadIdx.x;
    int warp = tid >> 5, lane = tid & 31;
    int colb = (warp & 3) * 32 + (lane & 7) * 4;
    int rowb = (warp >> 2) * 8 + (lane >> 3) * 2;
    int r0   = blockIdx.x * 16;

    const int nkt = NV / BK2;  // 64

    auto load_stage = [&](int s, int kt) {
        uint32_t base = sb + (uint32_t)(s * STG2_FLOATS) * 4u;
#pragma unroll
        for (int i = 0; i < 4; i++) {
            int c = i * 256 + tid;
            int row = c >> 5, cic = c & 31;
            cp_async16(base + (uint32_t)(row * D + cic * 4) * 4u,
                       g_HW + (size_t)(kt * BK2 + row) * D + cic * 4);
        }
        if (tid < 128) {
            int row = tid >> 3, cic = tid & 7;
            cp_async16(base + (uint32_t)(H_FLOATS + row * A_STRIDE + cic * 4) * 4u,
                       g_adjA + (size_t)(r0 + row) * NV + kt * BK2 + cic * 4);
        }
        cp_commit();
    };

    load_stage(0, 0);
    load_stage(1, 1);

    float4 acc0 = {0.f, 0.f, 0.f, 0.f};
    float4 acc1 = {0.f, 0.f, 0.f, 0.f};

    for (int kt = 0; kt < nkt; kt++) {
        if (kt + 1 < nkt) cp_wait1(); else cp_wait0();
        __syncthreads();
        int s = kt % NSTG2;
        if (kt + 2 < nkt) load_stage((kt + 2) % NSTG2, kt + 2);

        const float* sH = sm2 + s * STG2_FLOATS;
        const float* sA = sH + H_FLOATS;
        const float* a0p = sA + rowb * A_STRIDE;
        const float* a1p = a0p + A_STRIDE;

#pragma unroll
        for (int k4 = 0; k4 < BK2 / 4; k4++) {
            float4 a0 = *reinterpret_cast<const float4*>(a0p + k4 * 4);
            float4 a1 = *reinterpret_cast<const float4*>(a1p + k4 * 4);
#pragma unroll
            for (int kk = 0; kk < 4; kk++) {
                float4 h = *reinterpret_cast<const float4*>(sH + (k4 * 4 + kk) * D + colb);
                float av0 = (kk == 0) ? a0.x : (kk == 1) ? a0.y : (kk == 2) ? a0.z : a0.w;
                float av1 = (kk == 0) ? a1.x : (kk == 1) ? a1.y : (kk == 2) ? a1.z : a1.w;
                acc0.x += av0 * h.x; acc0.y += av0 * h.y;
                acc0.z += av0 * h.z; acc0.w += av0 * h.w;
                acc1.x += av1 * h.x; acc1.y += av1 * h.y;
                acc1.z += av1 * h.z; acc1.w += av1 * h.w;
            }
        }
    }

    float4 b = *reinterpret_cast<const float4*>(bias + colb);
    acc0.x += b.x; acc0.y += b.y; acc0.z += b.z; acc0.w += b.w;
    acc1.x += b.x; acc1.y += b.y; acc1.z += b.z; acc1.w += b.w;
    *reinterpret_cast<float4*>(out + (size_t)(r0 + rowb) * D + colb)     = acc0;
    *reinterpret_cast<float4*>(out + (size_t)(r0 + rowb + 1) * D + colb) = acc1;
}

// ---------------- launch ----------------
extern "C" void kernel_launch(void* const* d_in, const int* in_sizes, int n_in,
                              void* d_out, int out_size) {
    const float* H_v   = (const float*)d_in[0];
    const float* H_e   = (const float*)d_in[1];
    // d_in[2] = adj_e : UNUSED by the reference graph (node_layer branch)
    const float* adj_v = (const float*)d_in[3];
    const float* T     = (const float*)d_in[4];
    const float* W     = (const float*)d_in[5];
    const float* p     = (const float*)d_in[6];
    const float* bias  = (const float*)d_in[7];
    float* out = (float*)d_out;

    k_w<<<NE / 8, 256>>>(H_e, p);
    k_prep<<<2048, 256>>>(T);
    k_hw<<<NV / 8, 128>>>(H_v, W);

    cudaFuncSetAttribute(k_gemm1, cudaFuncAttributeMaxDynamicSharedMemorySize, SMEM_BYTES);
    k_gemm1<<<136, 512, SMEM_BYTES>>>(adj_v);

    cudaFuncSetAttribute(k_gemm2, cudaFuncAttributeMaxDynamicSharedMemorySize, SMEM2_BYTES);
    k_gemm2<<<NV / 16, 256, SMEM2_BYTES>>>(bias, out);

    // second output: H_e passthrough, concatenated after ret
    if (out_size >= NV * D + NE * D) {
        cudaMemcpyAsync(out + NV * D, H_e, (size_t)NE * D * sizeof(float),
                        cudaMemcpyDeviceToDevice, 0);
    }
}